// round 4
// baseline (speedup 1.0000x reference)
#include <cuda_runtime.h>
#include <cuda_bf16.h>
#include <cstdint>

// GraphConvolution: out[b,n,o] = sum_m adj[n,m] * (features[b,m,:] . W[o,:]) + bias[o]
// Strategy: big GEMM G = F[32768,1024] @ W^T[1024,256] with bf16x3 split-precision
// tensor-core MMA, then per-4-row adj mixing + bias in the epilogue.

#define BM 128
#define BN 128
#define BK 32
#define NTHREADS 256
#define KDIM 1024
#define ODIM 256
#define KITERS (KDIM / BK)

// smem: bf16 tiles with stride 40 (conflict-free for ldmatrix: 80B row stride)
#define ASTRIDE 40
#define EPISTRIDE 132

__device__ __forceinline__ void ldm4(uint32_t* r, const __nv_bfloat16* p) {
    uint32_t a = (uint32_t)__cvta_generic_to_shared(p);
    asm volatile("ldmatrix.sync.aligned.m8n8.x4.shared.b16 {%0,%1,%2,%3}, [%4];\n"
                 : "=r"(r[0]), "=r"(r[1]), "=r"(r[2]), "=r"(r[3])
                 : "r"(a));
}

__device__ __forceinline__ void mma16816(float* c, const uint32_t* a, const uint32_t* b) {
    asm volatile(
        "mma.sync.aligned.m16n8k16.row.col.f32.bf16.bf16.f32 "
        "{%0,%1,%2,%3}, {%4,%5,%6,%7}, {%8,%9}, {%0,%1,%2,%3};\n"
        : "+f"(c[0]), "+f"(c[1]), "+f"(c[2]), "+f"(c[3])
        : "r"(a[0]), "r"(a[1]), "r"(a[2]), "r"(a[3]), "r"(b[0]), "r"(b[1]));
}

__device__ __forceinline__ void split2(float x, float y, uint32_t& hi, uint32_t& lo) {
    __nv_bfloat16 hx = __float2bfloat16(x);
    __nv_bfloat16 hy = __float2bfloat16(y);
    __nv_bfloat16 lx = __float2bfloat16(x - __bfloat162float(hx));
    __nv_bfloat16 ly = __float2bfloat16(y - __bfloat162float(hy));
    hi = ((uint32_t)__bfloat16_as_ushort(hy) << 16) | (uint32_t)__bfloat16_as_ushort(hx);
    lo = ((uint32_t)__bfloat16_as_ushort(ly) << 16) | (uint32_t)__bfloat16_as_ushort(lx);
}

__global__ __launch_bounds__(NTHREADS, 1)
void gconv_kernel(const float* __restrict__ adj,
                  const float* __restrict__ feat,
                  const float* __restrict__ W,
                  const float* __restrict__ bias,
                  float* __restrict__ out) {
    // smem union: bf16 tiles (mainloop) / fp32 epilogue staging
    __shared__ __align__(16) unsigned char smem_raw[4 * BM * ASTRIDE * 2];  // 40960 B
    __shared__ float sAdj[16];

    __nv_bfloat16* sAh = (__nv_bfloat16*)smem_raw;
    __nv_bfloat16* sAl = sAh + BM * ASTRIDE;
    __nv_bfloat16* sWh = sAl + BM * ASTRIDE;
    __nv_bfloat16* sWl = sWh + BN * ASTRIDE;
    float* sEpi = (float*)smem_raw;  // 64 x EPISTRIDE fp32 = 33792 B, fits

    const int tid = threadIdx.x;
    const int lane = tid & 31;
    const int wid = tid >> 5;
    const int wm = wid >> 2;   // 0..1 -> warp M block of 64
    const int wn = wid & 3;    // 0..3 -> warp N block of 32
    const int mBaseW = wm * 64;
    const int nBaseW = wn * 32;

    const int mTileBase = blockIdx.y * BM;   // 0..32767 step 128
    const int nTileBase = blockIdx.x * BN;   // 0 or 128

    if (tid < 16) sAdj[tid] = adj[tid];

    // per-thread load layout: 4 float4 each for A and W tile (128x32 fp32)
    int rowIdx[4], colIdx[4];
#pragma unroll
    for (int i = 0; i < 4; i++) {
        int f = tid + i * NTHREADS;
        rowIdx[i] = f >> 3;          // 0..127
        colIdx[i] = (f & 7) * 4;     // 0..28
    }

    const float* Abase = feat + (size_t)mTileBase * KDIM;
    const float* Wbase = W + (size_t)nTileBase * KDIM;

    float4 ra[4], rw[4];
#pragma unroll
    for (int i = 0; i < 4; i++) {
        ra[i] = *(const float4*)(Abase + (size_t)rowIdx[i] * KDIM + colIdx[i]);
        rw[i] = *(const float4*)(Wbase + (size_t)rowIdx[i] * KDIM + colIdx[i]);
    }

    float acc[4][4][4] = {};  // [mtile][ntile][4]

    for (int it = 0; it < KITERS; ++it) {
        // split current regs into hi/lo bf16 smem tiles
#pragma unroll
        for (int i = 0; i < 4; i++) {
            int idx = rowIdx[i] * ASTRIDE + colIdx[i];
            uint32_t h01, l01, h23, l23;
            split2(ra[i].x, ra[i].y, h01, l01);
            split2(ra[i].z, ra[i].w, h23, l23);
            *(uint32_t*)&sAh[idx] = h01;
            *(uint32_t*)&sAh[idx + 2] = h23;
            *(uint32_t*)&sAl[idx] = l01;
            *(uint32_t*)&sAl[idx + 2] = l23;
            split2(rw[i].x, rw[i].y, h01, l01);
            split2(rw[i].z, rw[i].w, h23, l23);
            *(uint32_t*)&sWh[idx] = h01;
            *(uint32_t*)&sWh[idx + 2] = h23;
            *(uint32_t*)&sWl[idx] = l01;
            *(uint32_t*)&sWl[idx + 2] = l23;
        }
        // prefetch next K-slab into registers (overlaps with MMA below)
        if (it + 1 < KITERS) {
            const float* An = Abase + (it + 1) * BK;
            const float* Wn = Wbase + (it + 1) * BK;
#pragma unroll
            for (int i = 0; i < 4; i++) {
                ra[i] = *(const float4*)(An + (size_t)rowIdx[i] * KDIM + colIdx[i]);
                rw[i] = *(const float4*)(Wn + (size_t)rowIdx[i] * KDIM + colIdx[i]);
            }
        }
        __syncthreads();

#pragma unroll
        for (int ks = 0; ks < 2; ++ks) {
            uint32_t ah[4][4], al[4][4];
            uint32_t bh[4][2], bl[4][2];

            // A fragments: 4 mtiles of 16x16
            int arow = lane & 15;
            int acol = ks * 16 + (lane >> 4) * 8;
#pragma unroll
            for (int mt = 0; mt < 4; mt++) {
                const __nv_bfloat16* pa = sAh + (mBaseW + 16 * mt + arow) * ASTRIDE + acol;
                ldm4(ah[mt], pa);
                const __nv_bfloat16* pl = sAl + (mBaseW + 16 * mt + arow) * ASTRIDE + acol;
                ldm4(al[mt], pl);
            }
            // B fragments: 4 ntiles of n8k16, loaded as 2 x (n16k16)
            int bn = (lane & 7) + ((lane >> 4) << 3);
            int bk = ((lane >> 3) & 1) * 8;
#pragma unroll
            for (int np = 0; np < 2; np++) {
                uint32_t t[4];
                const __nv_bfloat16* pb = sWh + (nBaseW + 16 * np + bn) * ASTRIDE + ks * 16 + bk;
                ldm4(t, pb);
                bh[2 * np][0] = t[0]; bh[2 * np][1] = t[1];
                bh[2 * np + 1][0] = t[2]; bh[2 * np + 1][1] = t[3];
                const __nv_bfloat16* pbl = sWl + (nBaseW + 16 * np + bn) * ASTRIDE + ks * 16 + bk;
                ldm4(t, pbl);
                bl[2 * np][0] = t[0]; bl[2 * np][1] = t[1];
                bl[2 * np + 1][0] = t[2]; bl[2 * np + 1][1] = t[3];
            }

#pragma unroll
            for (int mt = 0; mt < 4; mt++) {
#pragma unroll
                for (int nt = 0; nt < 4; nt++) {
                    mma16816(acc[mt][nt], ah[mt], bh[nt]);  // hi*hi
                    mma16816(acc[mt][nt], ah[mt], bl[nt]);  // hi*lo
                    mma16816(acc[mt][nt], al[mt], bh[nt]);  // lo*hi
                }
            }
        }
        __syncthreads();
    }

    // ---- Epilogue: stage accums through smem, apply adj mix + bias ----
    const float4* bias4 = (const float4*)(bias + nTileBase);

#pragma unroll
    for (int p = 0; p < 2; ++p) {
        if (wm == p) {
#pragma unroll
            for (int mt = 0; mt < 4; mt++) {
#pragma unroll
                for (int nt = 0; nt < 4; nt++) {
                    int r0 = 16 * mt + (lane >> 2);
                    int c0 = nBaseW + 8 * nt + ((lane & 3) << 1);
                    sEpi[r0 * EPISTRIDE + c0]           = acc[mt][nt][0];
                    sEpi[r0 * EPISTRIDE + c0 + 1]       = acc[mt][nt][1];
                    sEpi[(r0 + 8) * EPISTRIDE + c0]     = acc[mt][nt][2];
                    sEpi[(r0 + 8) * EPISTRIDE + c0 + 1] = acc[mt][nt][3];
                }
            }
        }
        __syncthreads();

        // mix rows in groups of 4 (adj) + bias, store float4
#pragma unroll
        for (int q = 0; q < (64 * 32) / NTHREADS; ++q) {
            int idx = tid + q * NTHREADS;
            int r = idx >> 5;          // local row 0..63
            int c4 = idx & 31;         // float4 column 0..31
            int g = r & ~3;
            int n = r & 3;
            float4 v = bias4[c4];
#pragma unroll
            for (int m = 0; m < 4; m++) {
                float a = sAdj[n * 4 + m];
                float4 s = *(const float4*)&sEpi[(g + m) * EPISTRIDE + c4 * 4];
                v.x += a * s.x; v.y += a * s.y; v.z += a * s.z; v.w += a * s.w;
            }
            int grow = mTileBase + p * 64 + r;
            *(float4*)(out + (size_t)grow * ODIM + nTileBase + c4 * 4) = v;
        }
        __syncthreads();
    }
}

extern "C" void kernel_launch(void* const* d_in, const int* in_sizes, int n_in,
                              void* d_out, int out_size) {
    // identify inputs by element count (robust to ordering): adj=16,
    // features=33554432, W=262144, bias=256
    const float* adj = nullptr;
    const float* feat = nullptr;
    const float* W = nullptr;
    const float* bias = nullptr;
    int featElems = 8192 * 4 * 1024;
    for (int i = 0; i < n_in; i++) {
        if (in_sizes[i] == 16) adj = (const float*)d_in[i];
        else if (in_sizes[i] >= 1 << 20) { feat = (const float*)d_in[i]; featElems = in_sizes[i]; }
        else if (in_sizes[i] == 256 * 1024) W = (const float*)d_in[i];
        else if (in_sizes[i] == 256) bias = (const float*)d_in[i];
    }
    // positional fallback (metadata order: adj, features, W, b)
    if (!adj && n_in > 0) adj = (const float*)d_in[0];
    if (!feat && n_in > 1) feat = (const float*)d_in[1];
    if (!W && n_in > 2) W = (const float*)d_in[2];
    if (!bias && n_in > 3) bias = (const float*)d_in[3];

    int totalRows = featElems / KDIM;               // B*N = 32768 expected
    dim3 grid(ODIM / BN, (totalRows + BM - 1) / BM);  // (2, 256)
    dim3 block(NTHREADS);
    gconv_kernel<<<grid, block>>>(adj, feat, W, bias, (float*)d_out);
}

// round 9
// speedup vs baseline: 1.2523x; 1.2523x over previous
#include <cuda_runtime.h>
#include <cuda_bf16.h>
#include <cstdint>

// GraphConvolution: out[b,n,o] = sum_m adj[n,m]*(features[b,m,:].W[o,:]) + bias[o]
// G = F[32768,1024] @ W^T[1024,256] via bf16x3 split mma.sync (tcgen05 unavailable:
// harness PTX targets compute_103, no 'a' features). Optimized: 2 CTAs/SM,
// double-buffered smem (1 sync/iter), W pre-split once into device bf16 buffers.

#define KDIM 1024
#define ODIM 256
#define BM 64
#define BN 128
#define BK 32
#define KITERS (KDIM / BK)   // 32
#define NTH 256
#define ASTR 40              // bf16 row stride (80B) -> conflict-free ldmatrix
#define ESTR 132

// stage layout (bf16 elements): Ah | Al | Bh | Bl
#define T_AH 0
#define T_AL (BM * ASTR)                 // 2560
#define T_BH (2 * BM * ASTR)             // 5120
#define T_BL (2 * BM * ASTR + BN * ASTR) // 10240
#define STAGE_ELEMS (2 * BM * ASTR + 2 * BN * ASTR)  // 15360 bf16 = 30720 B
#define SMEM_BYTES (2 * STAGE_ELEMS * 2)             // 61440 B

__device__ __align__(16) __nv_bfloat16 g_Wh[ODIM * KDIM];
__device__ __align__(16) __nv_bfloat16 g_Wl[ODIM * KDIM];

__device__ __forceinline__ void ldm4(uint32_t* r, const __nv_bfloat16* p) {
    uint32_t a = (uint32_t)__cvta_generic_to_shared(p);
    asm volatile("ldmatrix.sync.aligned.m8n8.x4.shared.b16 {%0,%1,%2,%3}, [%4];\n"
                 : "=r"(r[0]), "=r"(r[1]), "=r"(r[2]), "=r"(r[3])
                 : "r"(a));
}

__device__ __forceinline__ void mma16816(float* c, const uint32_t* a, const uint32_t* b) {
    asm volatile(
        "mma.sync.aligned.m16n8k16.row.col.f32.bf16.bf16.f32 "
        "{%0,%1,%2,%3}, {%4,%5,%6,%7}, {%8,%9}, {%0,%1,%2,%3};\n"
        : "+f"(c[0]), "+f"(c[1]), "+f"(c[2]), "+f"(c[3])
        : "r"(a[0]), "r"(a[1]), "r"(a[2]), "r"(a[3]), "r"(b[0]), "r"(b[1]));
}

__device__ __forceinline__ void split2(float x, float y, uint32_t& hi, uint32_t& lo) {
    __nv_bfloat16 hx = __float2bfloat16(x);
    __nv_bfloat16 hy = __float2bfloat16(y);
    __nv_bfloat16 lx = __float2bfloat16(x - __bfloat162float(hx));
    __nv_bfloat16 ly = __float2bfloat16(y - __bfloat162float(hy));
    hi = ((uint32_t)__bfloat16_as_ushort(hy) << 16) | (uint32_t)__bfloat16_as_ushort(hx);
    lo = ((uint32_t)__bfloat16_as_ushort(ly) << 16) | (uint32_t)__bfloat16_as_ushort(lx);
}

__global__ void wsplit_kernel(const float* __restrict__ W) {
    int i = (blockIdx.x * blockDim.x + threadIdx.x) * 4;
    float4 v = *(const float4*)(W + i);
    uint32_t h01, l01, h23, l23;
    split2(v.x, v.y, h01, l01);
    split2(v.z, v.w, h23, l23);
    *(uint2*)(g_Wh + i) = make_uint2(h01, h23);
    *(uint2*)(g_Wl + i) = make_uint2(l01, l23);
}

__global__ __launch_bounds__(NTH, 2)
void gconv2(const float* __restrict__ adj,
            const float* __restrict__ feat,
            const float* __restrict__ bias,
            float* __restrict__ out) {
    extern __shared__ __align__(16) __nv_bfloat16 sm[];
    __shared__ float sAdj[16];

    const int tid = threadIdx.x;
    const int lane = tid & 31;
    const int wid = tid >> 5;
    const int wm = wid >> 2;          // 0..1 -> M block of 32
    const int wn = wid & 3;           // 0..3 -> N block of 32
    const int mTile = blockIdx.y * BM;
    const int nTile = blockIdx.x * BN;

    if (tid < 16) sAdj[tid] = adj[tid];

    // load mappings: A fp32 64x32 (2 float4/thread), B bf16 128x32 (2 uint4/thread/tile)
    const int rA0 = tid >> 3, cA0 = (tid & 7) * 4;
    const int rA1 = (tid + 256) >> 3;             // cA1 == cA0 (256 % 8 == 0)
    const int rB0 = tid >> 2, cB0 = (tid & 3) * 8;
    const int rB1 = (tid + 256) >> 2;             // cB1 == cB0

    const float* Af = feat + (size_t)mTile * KDIM;
    const __nv_bfloat16* WhB = g_Wh + (size_t)nTile * KDIM;
    const __nv_bfloat16* WlB = g_Wl + (size_t)nTile * KDIM;

    float4 ra0, ra1;
    uint4 wh0, wh1, wl0, wl1;

    // prologue: load chunk 0
    ra0 = *(const float4*)(Af + (size_t)rA0 * KDIM + cA0);
    ra1 = *(const float4*)(Af + (size_t)rA1 * KDIM + cA0);
    wh0 = *(const uint4*)(WhB + (size_t)rB0 * KDIM + cB0);
    wh1 = *(const uint4*)(WhB + (size_t)rB1 * KDIM + cB0);
    wl0 = *(const uint4*)(WlB + (size_t)rB0 * KDIM + cB0);
    wl1 = *(const uint4*)(WlB + (size_t)rB1 * KDIM + cB0);

    float acc[2][4][4] = {};   // [mt][nt][4]

    // store chunk 0 into stage 0
    {
        __nv_bfloat16* S = sm;
        uint32_t h01, l01, h23, l23;
        int ia = rA0 * ASTR + cA0;
        split2(ra0.x, ra0.y, h01, l01); split2(ra0.z, ra0.w, h23, l23);
        *(uint32_t*)&S[T_AH + ia] = h01; *(uint32_t*)&S[T_AH + ia + 2] = h23;
        *(uint32_t*)&S[T_AL + ia] = l01; *(uint32_t*)&S[T_AL + ia + 2] = l23;
        ia = rA1 * ASTR + cA0;
        split2(ra1.x, ra1.y, h01, l01); split2(ra1.z, ra1.w, h23, l23);
        *(uint32_t*)&S[T_AH + ia] = h01; *(uint32_t*)&S[T_AH + ia + 2] = h23;
        *(uint32_t*)&S[T_AL + ia] = l01; *(uint32_t*)&S[T_AL + ia + 2] = l23;
        *(uint4*)&S[T_BH + rB0 * ASTR + cB0] = wh0;
        *(uint4*)&S[T_BH + rB1 * ASTR + cB0] = wh1;
        *(uint4*)&S[T_BL + rB0 * ASTR + cB0] = wl0;
        *(uint4*)&S[T_BL + rB1 * ASTR + cB0] = wl1;
    }
    __syncthreads();

    for (int c = 0; c < KITERS; ++c) {
        // issue global loads for c+1 (latency overlapped with MMA below)
        if (c + 1 < KITERS) {
            const float* An = Af + (c + 1) * BK;
            const __nv_bfloat16* Whn = WhB + (c + 1) * BK;
            const __nv_bfloat16* Wln = WlB + (c + 1) * BK;
            ra0 = *(const float4*)(An + (size_t)rA0 * KDIM + cA0);
            ra1 = *(const float4*)(An + (size_t)rA1 * KDIM + cA0);
            wh0 = *(const uint4*)(Whn + (size_t)rB0 * KDIM + cB0);
            wh1 = *(const uint4*)(Whn + (size_t)rB1 * KDIM + cB0);
            wl0 = *(const uint4*)(Wln + (size_t)rB0 * KDIM + cB0);
            wl1 = *(const uint4*)(Wln + (size_t)rB1 * KDIM + cB0);
        }

        // MMA on stage c&1
        const __nv_bfloat16* S = sm + (c & 1) * STAGE_ELEMS;
#pragma unroll
        for (int ks = 0; ks < 2; ++ks) {
            uint32_t ah[2][4], al[2][4], bh[4][2], bl[4][2];
            int arow = lane & 15;
            int acol = ks * 16 + (lane >> 4) * 8;
#pragma unroll
            for (int mt = 0; mt < 2; mt++) {
                int rbase = (wm * 32 + 16 * mt + arow) * ASTR + acol;
                ldm4(ah[mt], &S[T_AH + rbase]);
                ldm4(al[mt], &S[T_AL + rbase]);
            }
            int bn = (lane & 7) + ((lane >> 4) << 3);
            int bk = ((lane >> 3) & 1) * 8;
#pragma unroll
            for (int np = 0; np < 2; np++) {
                uint32_t t[4];
                int bbase = (wn * 32 + 16 * np + bn) * ASTR + ks * 16 + bk;
                ldm4(t, &S[T_BH + bbase]);
                bh[2 * np][0] = t[0]; bh[2 * np][1] = t[1];
                bh[2 * np + 1][0] = t[2]; bh[2 * np + 1][1] = t[3];
                ldm4(t, &S[T_BL + bbase]);
                bl[2 * np][0] = t[0]; bl[2 * np][1] = t[1];
                bl[2 * np + 1][0] = t[2]; bl[2 * np + 1][1] = t[3];
            }
#pragma unroll
            for (int mt = 0; mt < 2; mt++) {
#pragma unroll
                for (int nt = 0; nt < 4; nt++) {
                    mma16816(acc[mt][nt], ah[mt], bh[nt]);
                    mma16816(acc[mt][nt], ah[mt], bl[nt]);
                    mma16816(acc[mt][nt], al[mt], bh[nt]);
                }
            }
        }

        // store chunk c+1 into the other stage
        if (c + 1 < KITERS) {
            __nv_bfloat16* D = sm + ((c + 1) & 1) * STAGE_ELEMS;
            uint32_t h01, l01, h23, l23;
            int ia = rA0 * ASTR + cA0;
            split2(ra0.x, ra0.y, h01, l01); split2(ra0.z, ra0.w, h23, l23);
            *(uint32_t*)&D[T_AH + ia] = h01; *(uint32_t*)&D[T_AH + ia + 2] = h23;
            *(uint32_t*)&D[T_AL + ia] = l01; *(uint32_t*)&D[T_AL + ia + 2] = l23;
            ia = rA1 * ASTR + cA0;
            split2(ra1.x, ra1.y, h01, l01); split2(ra1.z, ra1.w, h23, l23);
            *(uint32_t*)&D[T_AH + ia] = h01; *(uint32_t*)&D[T_AH + ia + 2] = h23;
            *(uint32_t*)&D[T_AL + ia] = l01; *(uint32_t*)&D[T_AL + ia + 2] = l23;
            *(uint4*)&D[T_BH + rB0 * ASTR + cB0] = wh0;
            *(uint4*)&D[T_BH + rB1 * ASTR + cB0] = wh1;
            *(uint4*)&D[T_BL + rB0 * ASTR + cB0] = wl0;
            *(uint4*)&D[T_BL + rB1 * ASTR + cB0] = wl1;
        }
        __syncthreads();
    }

    // ---- epilogue: stage 64x128 accums in smem, adj-mix + bias, store ----
    float* sEpi = (float*)sm;   // 64 x 132 fp32 = 33792 B (< 61440)
#pragma unroll
    for (int mt = 0; mt < 2; mt++) {
#pragma unroll
        for (int nt = 0; nt < 4; nt++) {
            int r0 = wm * 32 + 16 * mt + (lane >> 2);
            int c0 = wn * 32 + 8 * nt + ((lane & 3) << 1);
            sEpi[r0 * ESTR + c0]           = acc[mt][nt][0];
            sEpi[r0 * ESTR + c0 + 1]       = acc[mt][nt][1];
            sEpi[(r0 + 8) * ESTR + c0]     = acc[mt][nt][2];
            sEpi[(r0 + 8) * ESTR + c0 + 1] = acc[mt][nt][3];
        }
    }
    __syncthreads();

    const float4* bias4 = (const float4*)(bias + nTile);
#pragma unroll
    for (int q = 0; q < (BM * (BN / 4)) / NTH; ++q) {   // 8
        int idx = tid + q * NTH;
        int r = idx >> 5;           // 0..63
        int c4 = idx & 31;          // 0..31
        int g = r & ~3, n = r & 3;
        float4 v = bias4[c4];
#pragma unroll
        for (int m = 0; m < 4; m++) {
            float a = sAdj[n * 4 + m];
            float4 s = *(const float4*)&sEpi[(g + m) * ESTR + c4 * 4];
            v.x += a * s.x; v.y += a * s.y; v.z += a * s.z; v.w += a * s.w;
        }
        *(float4*)(out + (size_t)(mTile + r) * ODIM + nTile + c4 * 4) = v;
    }
}

extern "C" void kernel_launch(void* const* d_in, const int* in_sizes, int n_in,
                              void* d_out, int out_size) {
    const float* adj = nullptr;
    const float* feat = nullptr;
    const float* W = nullptr;
    const float* bias = nullptr;
    int featElems = 8192 * 4 * 1024;
    for (int i = 0; i < n_in; i++) {
        if (in_sizes[i] == 16) adj = (const float*)d_in[i];
        else if (in_sizes[i] >= 1 << 20) { feat = (const float*)d_in[i]; featElems = in_sizes[i]; }
        else if (in_sizes[i] == 256 * 1024) W = (const float*)d_in[i];
        else if (in_sizes[i] == 256) bias = (const float*)d_in[i];
    }
    if (!adj && n_in > 0) adj = (const float*)d_in[0];
    if (!feat && n_in > 1) feat = (const float*)d_in[1];
    if (!W && n_in > 2) W = (const float*)d_in[2];
    if (!bias && n_in > 3) bias = (const float*)d_in[3];

    // immediate, idempotent, capture-safe; no static guards (harness rule)
    cudaFuncSetAttribute(gconv2, cudaFuncAttributeMaxDynamicSharedMemorySize, SMEM_BYTES);

    // 1) pre-split W into bf16 hi/lo (1 MB total, L2-resident)
    wsplit_kernel<<<(ODIM * KDIM) / (256 * 4), 256>>>(W);

    // 2) main GEMM + adj epilogue
    int totalRows = featElems / KDIM;                 // 32768
    dim3 grid(ODIM / BN, totalRows / BM);             // (2, 512)
    gconv2<<<grid, NTH, SMEM_BYTES>>>(adj, feat, bias, (float*)d_out);
}